// round 5
// baseline (speedup 1.0000x reference)
#include <cuda_runtime.h>

// Reference = 0.5*mean(sigmoid(conv2d_valid(data, w4x4)+b)) + 0.5*qexp[b], per batch b.
// Quantum term is exactly 0: theta_i in {0, pi}; RX(pi) = -i*X and the CX chain are
// basis permutations / global phases acting on the UNIFORM state H^n|0>, which is
// invariant => P(q0=1) = 1/2 => qexp[b] = 0 for all b.
// So out[b] = 0.5*classical_mean (same scalar broadcast to all 256 outputs).

#define IMG 64
#define OUT 61
#define NPOS (OUT * OUT)          // 3721
#define NBATCH 256
#define THREADS 256

__device__ float        g_sum   = 0.0f;
__device__ unsigned int g_count = 0u;

__global__ __launch_bounds__(THREADS)
void conv_sigmoid_mean_kernel(const float* __restrict__ data,
                              const float* __restrict__ w,
                              const float* __restrict__ b,
                              float* __restrict__ out) {
    __shared__ float img[IMG * IMG];
    __shared__ float sw[16];
    __shared__ float warp_sums[THREADS / 32];
    __shared__ int   is_last;
    __shared__ float total;

    const int n   = blockIdx.x;
    const int tid = threadIdx.x;

    // Vectorized image load: 64*64 floats = 1024 float4
    const float4* src4 = reinterpret_cast<const float4*>(data + (size_t)n * IMG * IMG);
    float4* img4 = reinterpret_cast<float4*>(img);
    #pragma unroll
    for (int i = tid; i < IMG * IMG / 4; i += THREADS) {
        img4[i] = src4[i];
    }
    if (tid < 16) sw[tid] = w[tid];
    __syncthreads();

    const float bias = b[0];

    float lsum = 0.0f;
    for (int p = tid; p < NPOS; p += THREADS) {
        const int y = p / OUT;
        const int x = p - y * OUT;
        const float* row = img + y * IMG + x;
        float acc = bias;
        #pragma unroll
        for (int i = 0; i < 4; i++) {
            #pragma unroll
            for (int j = 0; j < 4; j++) {
                acc = fmaf(row[i * IMG + j], sw[i * 4 + j], acc);
            }
        }
        lsum += 1.0f / (1.0f + __expf(-acc));   // sigmoid
    }

    // warp reduce
    #pragma unroll
    for (int off = 16; off > 0; off >>= 1)
        lsum += __shfl_xor_sync(0xFFFFFFFFu, lsum, off);

    const int wid = tid >> 5;
    const int lid = tid & 31;
    if (lid == 0) warp_sums[wid] = lsum;
    __syncthreads();

    if (tid == 0) {
        float s = 0.0f;
        #pragma unroll
        for (int i = 0; i < THREADS / 32; i++) s += warp_sums[i];
        atomicAdd(&g_sum, s);
        __threadfence();
        unsigned int prev = atomicAdd(&g_count, 1u);
        is_last = (prev == (unsigned)(gridDim.x - 1)) ? 1 : 0;
        if (is_last) {
            // all prior blocks' g_sum adds are visible (fence-before-count)
            total = atomicAdd(&g_sum, 0.0f);
        }
    }
    __syncthreads();

    if (is_last) {
        const float scale = 0.5f / (float)(NBATCH * NPOS);
        const float val = total * scale;
        out[tid] = val;                     // THREADS == NBATCH == out_size
        if (tid == 0) {                     // self-clean for next graph replay
            g_sum   = 0.0f;
            g_count = 0u;
            __threadfence();
        }
    }
}

extern "C" void kernel_launch(void* const* d_in, const int* in_sizes, int n_in,
                              void* d_out, int out_size) {
    const float* data = (const float*)d_in[0];   // 256*1*64*64
    const float* w    = (const float*)d_in[1];   // 1*1*4*4
    const float* b    = (const float*)d_in[2];   // 1
    float* out = (float*)d_out;                  // 256 floats

    conv_sigmoid_mean_kernel<<<NBATCH, THREADS>>>(data, w, b, out);
}